// round 2
// baseline (speedup 1.0000x reference)
#include <cuda_runtime.h>
#include <math.h>

#define B_N   4096
#define M_N   8192
#define EMB   64
#define TAU   0.3f
#define NTHR  256

__device__ __forceinline__ float gelu_exact(float x) {
    return 0.5f * x * (1.0f + erff(x * 0.70710678118654752440f));
}

__device__ __forceinline__ void takemin(float& a, int& ai, float b, int bi) {
    if (b < a) { a = b; ai = bi; }
}
__device__ __forceinline__ void cmpswap(float& a, int& ai, float& b, int& bi) {
    if (b < a) { float t = a; a = b; b = t; int ti = ai; ai = bi; bi = ti; }
}

// insert (v, ix) into sorted ascending 4-list held in d0..d3 / j0..j3
#define INSERT4(v, ix)                                                  \
    if ((v) < d3) {                                                     \
        if ((v) < d2v) {                                                \
            d3 = d2v; j3 = j2;                                          \
            if ((v) < d1) {                                             \
                d2v = d1; j2 = j1;                                      \
                if ((v) < d0) { d1 = d0; j1 = j0; d0 = (v); j0 = (ix); }\
                else          { d1 = (v); j1 = (ix); }                  \
            } else { d2v = (v); j2 = (ix); }                            \
        } else { d3 = (v); j3 = (ix); }                                 \
    }

__global__ __launch_bounds__(NTHR) void anchor_knn_kernel(
    const float* __restrict__ nodes,   // (B,2,2)
    const float* __restrict__ ancS,    // (B,M,2)
    const float* __restrict__ ancL,    // (B,M,2)
    const float* __restrict__ W1,      // (64,2)
    const float* __restrict__ b1,      // (64,)
    const float* __restrict__ W2,      // (64,64)
    const float* __restrict__ b2,      // (64,)
    float* __restrict__ out)           // (2,B,64): hs then hl
{
    __shared__ float sW2t[EMB * 65];   // transposed W2, padded: sW2t[e*65+f] = W2[f*64+e]
    __shared__ float sh[4 * EMB];      // hidden activations / reused as contrib buffer
    __shared__ float scd[8 * 4];       // per-warp winner distances
    __shared__ int   sci[8 * 4];       // per-warp winner indices
    __shared__ float sta[4 * 2];       // top-4 anchor coords
    __shared__ float swt[4];           // softmax weights

    const int b    = blockIdx.x;
    const int side = blockIdx.y;
    const int tid  = threadIdx.x;
    const float* __restrict__ anc = side ? ancL : ancS;

    const float gx = nodes[b * 4 + side * 2 + 0];
    const float gy = nodes[b * 4 + side * 2 + 1];

    // Stage W2 transposed into smem
    #pragma unroll
    for (int i = tid; i < EMB * EMB; i += NTHR) {
        int f = i >> 6, e = i & 63;
        sW2t[e * 65 + f] = W2[i];
    }

    // ---- per-thread top-4 over this (b, side) anchor row ----
    float d0 = 3.0e38f, d1 = 3.0e38f, d2v = 3.0e38f, d3 = 3.0e38f;
    int   j0 = 0, j1 = 0, j2 = 0, j3 = 0;

    const float4* __restrict__ a4 =
        reinterpret_cast<const float4*>(anc + (size_t)b * (M_N * 2));
    #pragma unroll 4
    for (int i = tid; i < (M_N * 2) / 4; i += NTHR) {
        float4 v = a4[i];
        float ax = v.x - gx, ay = v.y - gy;
        float da = fmaf(ax, ax, ay * ay);
        float bx = v.z - gx, by = v.w - gy;
        float db = fmaf(bx, bx, by * by);
        int ia = 2 * i, ib = 2 * i + 1;
        INSERT4(da, ia);
        INSERT4(db, ib);
    }

    // ---- warp reduction: merge sorted 4-lists (bitonic-merge lower half) ----
    const unsigned full = 0xffffffffu;
    #pragma unroll
    for (int off = 16; off > 0; off >>= 1) {
        float e0 = __shfl_down_sync(full, d0,  off);
        float e1 = __shfl_down_sync(full, d1,  off);
        float e2 = __shfl_down_sync(full, d2v, off);
        float e3 = __shfl_down_sync(full, d3,  off);
        int   k0 = __shfl_down_sync(full, j0,  off);
        int   k1 = __shfl_down_sync(full, j1,  off);
        int   k2 = __shfl_down_sync(full, j2,  off);
        int   k3 = __shfl_down_sync(full, j3,  off);
        takemin(d0,  j0, e3, k3);
        takemin(d1,  j1, e2, k2);
        takemin(d2v, j2, e1, k1);
        takemin(d3,  j3, e0, k0);
        cmpswap(d0,  j0, d2v, j2);
        cmpswap(d1,  j1, d3,  j3);
        cmpswap(d0,  j0, d1,  j1);
        cmpswap(d2v, j2, d3,  j3);
    }

    const int wid = tid >> 5, lane = tid & 31;
    if (lane == 0) {
        scd[wid * 4 + 0] = d0;  sci[wid * 4 + 0] = j0;
        scd[wid * 4 + 1] = d1;  sci[wid * 4 + 1] = j1;
        scd[wid * 4 + 2] = d2v; sci[wid * 4 + 2] = j2;
        scd[wid * 4 + 3] = d3;  sci[wid * 4 + 3] = j3;
    }
    __syncthreads();

    // ---- final merge + softmax weights + coord gather (thread 0, serial) ----
    if (tid == 0) {
        float fd[4] = {3.0e38f, 3.0e38f, 3.0e38f, 3.0e38f};
        int   fi[4] = {0, 0, 0, 0};
        for (int q = 0; q < 32; q++) {
            float v = scd[q]; int ix = sci[q];
            if (v < fd[3]) {
                int p = 3;
                while (p > 0 && v < fd[p - 1]) { fd[p] = fd[p - 1]; fi[p] = fi[p - 1]; p--; }
                fd[p] = v; fi[p] = ix;
            }
        }
        // softmax(vals / -tau), vals = -d2  =>  logits = d2 / tau
        const float inv_tau = 1.0f / TAU;
        float mx = fd[3] * inv_tau;  // largest logit
        float e0 = expf(fd[0] * inv_tau - mx);
        float e1 = expf(fd[1] * inv_tau - mx);
        float e2 = expf(fd[2] * inv_tau - mx);
        float e3 = expf(fd[3] * inv_tau - mx);
        float inv_s = 1.0f / (e0 + e1 + e2 + e3);
        swt[0] = e0 * inv_s; swt[1] = e1 * inv_s;
        swt[2] = e2 * inv_s; swt[3] = e3 * inv_s;
        const float* base = anc + (size_t)b * (M_N * 2);
        #pragma unroll
        for (int q = 0; q < 4; q++) {
            sta[q * 2 + 0] = base[fi[q] * 2 + 0];
            sta[q * 2 + 1] = base[fi[q] * 2 + 1];
        }
    }
    __syncthreads();

    // ---- MLP stage A: h[k][e] = gelu(a.x*W1[e,0] + a.y*W1[e,1] + b1[e]) ----
    const int k = tid >> 6, f = tid & 63;
    {
        float ax = sta[k * 2 + 0], ay = sta[k * 2 + 1];
        float hv = fmaf(ax, __ldg(&W1[f * 2 + 0]),
                   fmaf(ay, __ldg(&W1[f * 2 + 1]), __ldg(&b1[f])));
        sh[k * 64 + f] = gelu_exact(hv);
    }
    __syncthreads();

    // ---- MLP stage B: o[k][f] = gelu(sum_e h[k][e] * W2[f][e] + b2[f]) ----
    float acc = __ldg(&b2[f]);
    {
        const float* __restrict__ hrow = &sh[k * 64];
        #pragma unroll
        for (int e = 0; e < EMB; e++)
            acc = fmaf(hrow[e], sW2t[e * 65 + f], acc);
    }
    float contrib = gelu_exact(acc) * swt[k];
    __syncthreads();              // all reads of sh done
    sh[tid] = contrib;            // reuse as contribution buffer
    __syncthreads();

    if (tid < 64) {
        float r = sh[tid] + sh[64 + tid] + sh[128 + tid] + sh[192 + tid];
        out[((size_t)side * B_N + b) * 64 + tid] = r;
    }
}

extern "C" void kernel_launch(void* const* d_in, const int* in_sizes, int n_in,
                              void* d_out, int out_size) {
    const float* nodes = (const float*)d_in[0];
    const float* ancS  = (const float*)d_in[1];
    const float* ancL  = (const float*)d_in[2];
    const float* W1    = (const float*)d_in[3];
    const float* b1    = (const float*)d_in[4];
    const float* W2    = (const float*)d_in[5];
    const float* b2    = (const float*)d_in[6];
    float* out = (float*)d_out;

    dim3 grid(B_N, 2);
    anchor_knn_kernel<<<grid, NTHR>>>(nodes, ancS, ancL, W1, b1, W2, b2, out);
}